// round 1
// baseline (speedup 1.0000x reference)
#include <cuda_runtime.h>
#include <math.h>

#define BATCH 2
#define SQ 2048
#define NH 16
#define DK 64
#define DMODEL 1024
#define NREL 4095   // relative positions -2047..2047

// Scratch (allocation-free rules: __device__ globals)
__device__ float g_q[BATCH*NH*SQ*DK];
__device__ float g_k[BATCH*NH*SQ*DK];
__device__ float g_v[BATCH*NH*SQ*DK];
__device__ float g_ctx[(size_t)BATCH*SQ*DMODEL];
__device__ float g_bias[NH*NREL];

// ---------------------------------------------------------------------------
// T5 relative-position bias table: g_bias[h][rel + 2047]
// Mirrors reference float ops exactly: 8 + int(logf(rp/8)/logf(16)*8), min 15.
// ---------------------------------------------------------------------------
__global__ void bias_kernel(const float* __restrict__ emb) {
    int idx = blockIdx.x * blockDim.x + threadIdx.x;
    if (idx >= NREL) return;
    int rel = idx - (SQ - 1);            // mem - ctx
    int bucket = (rel > 0) ? 16 : 0;     // num_buckets//2
    int rp = rel < 0 ? -rel : rel;
    int add;
    if (rp < 8) {
        add = rp;
    } else {
        float t = logf((float)rp * 0.125f);
        float u = t / 2.772588722239781f;    // log(128/8) as float32
        float v = u * 8.0f;                  // * (nb - max_exact)
        int w = 8 + (int)v;
        add = w < 15 ? w : 15;
    }
    bucket += add;
#pragma unroll
    for (int h = 0; h < NH; h++)
        g_bias[h * NREL + idx] = emb[bucket * NH + h];
}

// ---------------------------------------------------------------------------
// fp32 GEMM: C[M=4096, NSZ] = A[4096,1024] @ B[1024,NSZ]
// 64x64 CTA tile, BK=16, 256 threads, 4x4 register micro-tile.
// MODE 0: scatter to g_q/g_k/g_v head-major; MODE 1: plain write to Cout.
// ---------------------------------------------------------------------------
template <int NSZ, int MODE>
__global__ __launch_bounds__(256)
void gemm_kernel(const float* __restrict__ A, const float* __restrict__ B,
                 float* __restrict__ Cout) {
    __shared__ __align__(16) float AsT[16][68];  // [k][m]
    __shared__ __align__(16) float Bs[16][68];   // [k][n]

    const int n0 = blockIdx.x * 64;
    const int m0 = blockIdx.y * 64;
    const int tid = threadIdx.x;
    const int ty = tid >> 4, tx = tid & 15;

    const float* Abase = (MODE == 0) ? A : (const float*)g_ctx;
    const float* Ap = Abase + (size_t)m0 * 1024;
    const float* Bp = B + n0;

    const int ar = tid >> 2, ac = tid & 3;    // A loader: row 0..63, float4 col 0..3
    const int br = tid >> 4, bc = tid & 15;   // B loader: row 0..15, float4 col 0..15

    float acc[4][4];
#pragma unroll
    for (int i = 0; i < 4; i++)
#pragma unroll
        for (int j = 0; j < 4; j++) acc[i][j] = 0.f;

    for (int k0 = 0; k0 < 1024; k0 += 16) {
        float4 av = *(const float4*)(Ap + (size_t)ar * 1024 + k0 + ac * 4);
        float4 bv = *(const float4*)(Bp + (size_t)(k0 + br) * NSZ + bc * 4);
        AsT[ac * 4 + 0][ar] = av.x;
        AsT[ac * 4 + 1][ar] = av.y;
        AsT[ac * 4 + 2][ar] = av.z;
        AsT[ac * 4 + 3][ar] = av.w;
        *(float4*)(&Bs[br][bc * 4]) = bv;
        __syncthreads();
#pragma unroll
        for (int kk = 0; kk < 16; kk++) {
            float4 a = *(const float4*)(&AsT[kk][ty * 4]);
            float4 b = *(const float4*)(&Bs[kk][tx * 4]);
            float ax[4] = {a.x, a.y, a.z, a.w};
            float bx[4] = {b.x, b.y, b.z, b.w};
#pragma unroll
            for (int i = 0; i < 4; i++)
#pragma unroll
                for (int j = 0; j < 4; j++) acc[i][j] += ax[i] * bx[j];
        }
        __syncthreads();
    }

    if (MODE == 0) {
        // n tile lies entirely within one of q/k/v and one head (64 | 1024)
        const int part = n0 >> 10;
        const int h = (n0 & 1023) >> 6;
        float* dst = (part == 0) ? g_q : (part == 1) ? g_k : g_v;
#pragma unroll
        for (int i = 0; i < 4; i++) {
            int gm = m0 + ty * 4 + i;
            int b = gm >> 11, s = gm & 2047;
            float* row = dst + ((size_t)((b * NH + h) * SQ) + s) * DK;
            float4 w = make_float4(acc[i][0], acc[i][1], acc[i][2], acc[i][3]);
            *(float4*)(row + tx * 4) = w;
        }
    } else {
#pragma unroll
        for (int i = 0; i < 4; i++) {
            int gm = m0 + ty * 4 + i;
            float4 w = make_float4(acc[i][0], acc[i][1], acc[i][2], acc[i][3]);
            *(float4*)(Cout + (size_t)gm * NSZ + n0 + tx * 4) = w;
        }
    }
}

// ---------------------------------------------------------------------------
// Flash-style attention per (b, h, 64-query block).
// SMEM: QsT[d][q], KsT[d][k], Vs[k][d], Ss[q][k] (all pitch 68), row stats.
// ---------------------------------------------------------------------------
__global__ __launch_bounds__(256)
void attn_kernel(const float* __restrict__ mask) {
    extern __shared__ float sm[];
    float* QsT = sm;              // 64*68
    float* KsT = sm + 4352;
    float* Vs  = sm + 8704;
    float* Ss  = sm + 13056;
    float* rowm = sm + 17408;     // 64
    float* rowl = rowm + 64;
    float* rowa = rowl + 64;

    const int q0 = blockIdx.x * 64;
    const int h  = blockIdx.y;
    const int b  = blockIdx.z;
    const int tid = threadIdx.x;
    const int ty = tid >> 4, tx = tid & 15;

    const float* Qg = g_q + ((size_t)(b * NH + h) * SQ + q0) * DK;
    const float* Kg = g_k + (size_t)(b * NH + h) * SQ * DK;
    const float* Vg = g_v + (size_t)(b * NH + h) * SQ * DK;
    const float* Mg = mask + (size_t)b * SQ * SQ;
    const float* Bg = g_bias + h * NREL;

    // Load Q tile transposed: QsT[d][q]
#pragma unroll
    for (int t = 0; t < 4; t++) {
        int idx = tid + t * 256;
        int r = idx >> 4, c4 = idx & 15;
        float4 v = *(const float4*)(Qg + r * DK + c4 * 4);
        QsT[(c4 * 4 + 0) * 68 + r] = v.x;
        QsT[(c4 * 4 + 1) * 68 + r] = v.y;
        QsT[(c4 * 4 + 2) * 68 + r] = v.z;
        QsT[(c4 * 4 + 3) * 68 + r] = v.w;
    }
    if (tid < 64) { rowm[tid] = -3.0e38f; rowl[tid] = 0.f; }

    float o[4][4];
#pragma unroll
    for (int i = 0; i < 4; i++)
#pragma unroll
        for (int j = 0; j < 4; j++) o[i][j] = 0.f;

    for (int k0 = 0; k0 < SQ; k0 += 64) {
        // Load K (transposed) and V tiles
#pragma unroll
        for (int t = 0; t < 4; t++) {
            int idx = tid + t * 256;
            int r = idx >> 4, c4 = idx & 15;
            float4 kv = *(const float4*)(Kg + (size_t)(k0 + r) * DK + c4 * 4);
            KsT[(c4 * 4 + 0) * 68 + r] = kv.x;
            KsT[(c4 * 4 + 1) * 68 + r] = kv.y;
            KsT[(c4 * 4 + 2) * 68 + r] = kv.z;
            KsT[(c4 * 4 + 3) * 68 + r] = kv.w;
            float4 vv = *(const float4*)(Vg + (size_t)(k0 + r) * DK + c4 * 4);
            *(float4*)(Vs + r * 68 + c4 * 4) = vv;
        }
        __syncthreads();

        // S = Q K^T (4x4 per thread)
        float s[4][4];
#pragma unroll
        for (int i = 0; i < 4; i++)
#pragma unroll
            for (int j = 0; j < 4; j++) s[i][j] = 0.f;
#pragma unroll 16
        for (int d = 0; d < 64; d++) {
            float4 qv = *(const float4*)(QsT + d * 68 + ty * 4);
            float4 kv = *(const float4*)(KsT + d * 68 + tx * 4);
            float qa[4] = {qv.x, qv.y, qv.z, qv.w};
            float ka[4] = {kv.x, kv.y, kv.z, kv.w};
#pragma unroll
            for (int i = 0; i < 4; i++)
#pragma unroll
                for (int j = 0; j < 4; j++) s[i][j] += qa[i] * ka[j];
        }

        // scale + mask + bias -> Ss
#pragma unroll
        for (int i = 0; i < 4; i++) {
            int q = q0 + ty * 4 + i;
            int kbase = k0 + tx * 4;
            float4 mv = *(const float4*)(Mg + (size_t)q * SQ + kbase);
            const float* brow = Bg + (kbase - q + (SQ - 1));
            float ma[4] = {mv.x, mv.y, mv.z, mv.w};
            float4 outv;
            float* po = (float*)&outv;
#pragma unroll
            for (int j = 0; j < 4; j++) {
                po[j] = s[i][j] * 0.125f * ma[j] +
                        (brow[j] - 10000.0f * (1.0f - ma[j]));
            }
            *(float4*)(Ss + (ty * 4 + i) * 68 + tx * 4) = outv;
        }
        __syncthreads();

        // Online softmax: 4 lanes per row
        {
            int row = tid >> 2, c4 = tid & 3;
            float* srow = Ss + row * 68 + c4 * 16;
            float4 v0 = *(float4*)(srow);
            float4 v1 = *(float4*)(srow + 4);
            float4 v2 = *(float4*)(srow + 8);
            float4 v3 = *(float4*)(srow + 12);
            float tmax = fmaxf(fmaxf(fmaxf(v0.x, v0.y), fmaxf(v0.z, v0.w)),
                        fmaxf(fmaxf(fmaxf(v1.x, v1.y), fmaxf(v1.z, v1.w)),
                        fmaxf(fmaxf(fmaxf(v2.x, v2.y), fmaxf(v2.z, v2.w)),
                              fmaxf(fmaxf(v3.x, v3.y), fmaxf(v3.z, v3.w)))));
            tmax = fmaxf(tmax, __shfl_xor_sync(0xffffffffu, tmax, 1));
            tmax = fmaxf(tmax, __shfl_xor_sync(0xffffffffu, tmax, 2));
            float mold = rowm[row];
            float mnew = fmaxf(mold, tmax);
            float alpha = __expf(mold - mnew);
            v0.x = __expf(v0.x - mnew); v0.y = __expf(v0.y - mnew);
            v0.z = __expf(v0.z - mnew); v0.w = __expf(v0.w - mnew);
            v1.x = __expf(v1.x - mnew); v1.y = __expf(v1.y - mnew);
            v1.z = __expf(v1.z - mnew); v1.w = __expf(v1.w - mnew);
            v2.x = __expf(v2.x - mnew); v2.y = __expf(v2.y - mnew);
            v2.z = __expf(v2.z - mnew); v2.w = __expf(v2.w - mnew);
            v3.x = __expf(v3.x - mnew); v3.y = __expf(v3.y - mnew);
            v3.z = __expf(v3.z - mnew); v3.w = __expf(v3.w - mnew);
            float psum = (v0.x + v0.y + v0.z + v0.w) + (v1.x + v1.y + v1.z + v1.w)
                       + (v2.x + v2.y + v2.z + v2.w) + (v3.x + v3.y + v3.z + v3.w);
            psum += __shfl_xor_sync(0xffffffffu, psum, 1);
            psum += __shfl_xor_sync(0xffffffffu, psum, 2);
            *(float4*)(srow)      = v0;
            *(float4*)(srow + 4)  = v1;
            *(float4*)(srow + 8)  = v2;
            *(float4*)(srow + 12) = v3;
            if (c4 == 0) {
                rowl[row] = rowl[row] * alpha + psum;
                rowm[row] = mnew;
                rowa[row] = alpha;
            }
        }
        __syncthreads();

        // Rescale accumulators + O += P V
        float a0 = rowa[ty * 4 + 0], a1 = rowa[ty * 4 + 1];
        float a2 = rowa[ty * 4 + 2], a3 = rowa[ty * 4 + 3];
#pragma unroll
        for (int j = 0; j < 4; j++) {
            o[0][j] *= a0; o[1][j] *= a1; o[2][j] *= a2; o[3][j] *= a3;
        }
#pragma unroll 8
        for (int kk = 0; kk < 64; kk++) {
            float4 vv = *(const float4*)(Vs + kk * 68 + tx * 4);
            float va[4] = {vv.x, vv.y, vv.z, vv.w};
            float p0 = Ss[(ty * 4 + 0) * 68 + kk];
            float p1 = Ss[(ty * 4 + 1) * 68 + kk];
            float p2 = Ss[(ty * 4 + 2) * 68 + kk];
            float p3 = Ss[(ty * 4 + 3) * 68 + kk];
#pragma unroll
            for (int j = 0; j < 4; j++) {
                o[0][j] += p0 * va[j];
                o[1][j] += p1 * va[j];
                o[2][j] += p2 * va[j];
                o[3][j] += p3 * va[j];
            }
        }
        __syncthreads();
    }

    // Finalize: O / l, write ctx in [b][s][h*64+d] layout for the output GEMM
#pragma unroll
    for (int i = 0; i < 4; i++) {
        int q = q0 + ty * 4 + i;
        float linv = 1.0f / rowl[ty * 4 + i];
        float4 w = make_float4(o[i][0] * linv, o[i][1] * linv,
                               o[i][2] * linv, o[i][3] * linv);
        *(float4*)(g_ctx + (size_t)(b * SQ + q) * DMODEL + h * DK + tx * 4) = w;
    }
}

// ---------------------------------------------------------------------------
extern "C" void kernel_launch(void* const* d_in, const int* in_sizes, int n_in,
                              void* d_out, int out_size) {
    (void)in_sizes; (void)n_in; (void)out_size;
    const float* hidden = (const float*)d_in[0];
    const float* mask   = (const float*)d_in[1];
    const float* Wqkv   = (const float*)d_in[2];
    const float* Wo     = (const float*)d_in[3];
    const float* emb    = (const float*)d_in[4];
    float* out = (float*)d_out;

    // 1) Bias table
    bias_kernel<<<16, 256>>>(emb);

    // 2) QKV projection + head-major scatter
    gemm_kernel<3072, 0><<<dim3(48, 64), 256>>>(hidden, Wqkv, nullptr);

    // 3) Attention (flash-style, online softmax)
    const int smem_bytes = 17600 * 4;  // 70400 B
    cudaFuncSetAttribute(attn_kernel, cudaFuncAttributeMaxDynamicSharedMemorySize,
                         smem_bytes);
    attn_kernel<<<dim3(SQ / 64, NH, BATCH), 256, smem_bytes>>>(mask);

    // 4) Output projection
    gemm_kernel<1024, 1><<<dim3(16, 64), 256>>>(nullptr, Wo, out);
}

// round 2
// speedup vs baseline: 2.3294x; 2.3294x over previous
#include <cuda_runtime.h>
#include <math.h>

#define BATCH 2
#define SQ 2048
#define NH 16
#define DK 64
#define DMODEL 1024
#define NREL 4095   // relative positions -2047..2047

// Scratch (allocation-free rules: __device__ globals)
__device__ float g_q[BATCH*NH*SQ*DK];
__device__ float g_k[BATCH*NH*SQ*DK];
__device__ float g_v[BATCH*NH*SQ*DK];
__device__ float g_ctx[(size_t)BATCH*SQ*DMODEL];
__device__ float g_bias[NH*NREL];

// ---------------------------------------------------------------------------
// Helpers: tf32 convert + m16n8k8 tf32 mma
// ---------------------------------------------------------------------------
__device__ __forceinline__ float f2tf32(float x) {
    unsigned r;
    asm("cvt.rna.tf32.f32 %0, %1;" : "=r"(r) : "f"(x));
    return __uint_as_float(r);
}

__device__ __forceinline__ void mma_tf32(float c[4], const unsigned a[4],
                                         const unsigned b[2]) {
    asm volatile(
        "mma.sync.aligned.m16n8k8.row.col.f32.tf32.tf32.f32 "
        "{%0,%1,%2,%3}, {%4,%5,%6,%7}, {%8,%9}, {%0,%1,%2,%3};\n"
        : "+f"(c[0]), "+f"(c[1]), "+f"(c[2]), "+f"(c[3])
        : "r"(a[0]), "r"(a[1]), "r"(a[2]), "r"(a[3]), "r"(b[0]), "r"(b[1]));
}

// ---------------------------------------------------------------------------
// T5 relative-position bias table: g_bias[h][rel + 2047]
// ---------------------------------------------------------------------------
__global__ void bias_kernel(const float* __restrict__ emb) {
    int idx = blockIdx.x * blockDim.x + threadIdx.x;
    if (idx >= NREL) return;
    int rel = idx - (SQ - 1);            // mem - ctx
    int bucket = (rel > 0) ? 16 : 0;
    int rp = rel < 0 ? -rel : rel;
    int add;
    if (rp < 8) {
        add = rp;
    } else {
        float t = logf((float)rp * 0.125f);
        float u = t / 2.772588722239781f;    // log(128/8)
        float v = u * 8.0f;
        int w = 8 + (int)v;
        add = w < 15 ? w : 15;
    }
    bucket += add;
#pragma unroll
    for (int h = 0; h < NH; h++)
        g_bias[h * NREL + idx] = emb[bucket * NH + h];
}

// ---------------------------------------------------------------------------
// TF32 tensor-core GEMM: C[4096, NSZ] = A[4096,1024] @ B[1024,NSZ]
// CTA tile 128x128, BK=16, 256 threads = 8 warps (2x4), warp tile 64x32.
// MODE 0: scatter to g_q/g_k/g_v head-major; MODE 1: plain write to Cout.
// ---------------------------------------------------------------------------
#define AP 20    // As pitch (words): (20*r)%32 cycles all groups -> conflict-free
#define BP 136   // Bs pitch: (136*k)%32 = 8k -> conflict-free with n in low 3 bits

template <int NSZ, int MODE>
__global__ __launch_bounds__(256)
void gemm_tc(const float* __restrict__ A, const float* __restrict__ B,
             float* __restrict__ Cout) {
    __shared__ float As[128 * AP];   // [m][k] pitch 20
    __shared__ float Bs[16 * BP];    // [k][n] pitch 136

    const int n0 = blockIdx.x * 128;
    const int m0 = blockIdx.y * 128;
    const int tid = threadIdx.x;
    const int warp = tid >> 5, lane = tid & 31;
    const int wy = warp >> 2, wx = warp & 3;       // warp tile: rows wy*64, cols wx*32
    const int lr = lane >> 2, lc = lane & 3;

    const float* Abase = (MODE == 0) ? A : (const float*)g_ctx;
    const float* Ap = Abase + (size_t)m0 * 1024;
    const float* Bp = B + n0;

    // loader mapping: float4 id f = 2*tid + {0,1}
    const int fa = 2 * tid;
    const int a_row0 = fa >> 2,      a_c0 = (fa & 3) * 4;
    const int a_row1 = (fa + 1) >> 2, a_c1 = ((fa + 1) & 3) * 4;
    const int b_row0 = fa >> 5,      b_c0 = (fa & 31) * 4;
    const int b_row1 = (fa + 1) >> 5, b_c1 = ((fa + 1) & 31) * 4;

    float acc[4][4][4];
#pragma unroll
    for (int i = 0; i < 4; i++)
#pragma unroll
        for (int j = 0; j < 4; j++)
#pragma unroll
            for (int r = 0; r < 4; r++) acc[i][j][r] = 0.f;

    float4 pa0, pa1, pb0, pb1;
    // prefetch k0 = 0
    pa0 = *(const float4*)(Ap + (size_t)a_row0 * 1024 + a_c0);
    pa1 = *(const float4*)(Ap + (size_t)a_row1 * 1024 + a_c1);
    pb0 = *(const float4*)(Bp + (size_t)b_row0 * NSZ + b_c0);
    pb1 = *(const float4*)(Bp + (size_t)b_row1 * NSZ + b_c1);

    for (int k0 = 0; k0 < 1024; k0 += 16) {
        // store prefetched tile (tf32-rounded)
        As[a_row0 * AP + a_c0 + 0] = f2tf32(pa0.x);
        As[a_row0 * AP + a_c0 + 1] = f2tf32(pa0.y);
        As[a_row0 * AP + a_c0 + 2] = f2tf32(pa0.z);
        As[a_row0 * AP + a_c0 + 3] = f2tf32(pa0.w);
        As[a_row1 * AP + a_c1 + 0] = f2tf32(pa1.x);
        As[a_row1 * AP + a_c1 + 1] = f2tf32(pa1.y);
        As[a_row1 * AP + a_c1 + 2] = f2tf32(pa1.z);
        As[a_row1 * AP + a_c1 + 3] = f2tf32(pa1.w);
        Bs[b_row0 * BP + b_c0 + 0] = f2tf32(pb0.x);
        Bs[b_row0 * BP + b_c0 + 1] = f2tf32(pb0.y);
        Bs[b_row0 * BP + b_c0 + 2] = f2tf32(pb0.z);
        Bs[b_row0 * BP + b_c0 + 3] = f2tf32(pb0.w);
        Bs[b_row1 * BP + b_c1 + 0] = f2tf32(pb1.x);
        Bs[b_row1 * BP + b_c1 + 1] = f2tf32(pb1.y);
        Bs[b_row1 * BP + b_c1 + 2] = f2tf32(pb1.z);
        Bs[b_row1 * BP + b_c1 + 3] = f2tf32(pb1.w);
        __syncthreads();

        if (k0 + 16 < 1024) {
            pa0 = *(const float4*)(Ap + (size_t)a_row0 * 1024 + k0 + 16 + a_c0);
            pa1 = *(const float4*)(Ap + (size_t)a_row1 * 1024 + k0 + 16 + a_c1);
            pb0 = *(const float4*)(Bp + (size_t)(k0 + 16 + b_row0) * NSZ + b_c0);
            pb1 = *(const float4*)(Bp + (size_t)(k0 + 16 + b_row1) * NSZ + b_c1);
        }

#pragma unroll
        for (int ks = 0; ks < 2; ks++) {
            unsigned af[4][4], bf[4][2];
#pragma unroll
            for (int mt = 0; mt < 4; mt++) {
                int r0 = wy * 64 + mt * 16 + lr;
                af[mt][0] = __float_as_uint(As[r0 * AP + ks * 8 + lc]);
                af[mt][1] = __float_as_uint(As[(r0 + 8) * AP + ks * 8 + lc]);
                af[mt][2] = __float_as_uint(As[r0 * AP + ks * 8 + lc + 4]);
                af[mt][3] = __float_as_uint(As[(r0 + 8) * AP + ks * 8 + lc + 4]);
            }
#pragma unroll
            for (int nt = 0; nt < 4; nt++) {
                int n = wx * 32 + nt * 8 + lr;
                bf[nt][0] = __float_as_uint(Bs[(ks * 8 + lc) * BP + n]);
                bf[nt][1] = __float_as_uint(Bs[(ks * 8 + lc + 4) * BP + n]);
            }
#pragma unroll
            for (int mt = 0; mt < 4; mt++)
#pragma unroll
                for (int nt = 0; nt < 4; nt++)
                    mma_tf32(acc[mt][nt], af[mt], bf[nt]);
        }
        __syncthreads();
    }

    // epilogue
#pragma unroll
    for (int mt = 0; mt < 4; mt++) {
        int gm0 = m0 + wy * 64 + mt * 16 + lr;
#pragma unroll
        for (int nt = 0; nt < 4; nt++) {
            int gn = n0 + wx * 32 + nt * 8 + 2 * lc;
            if (MODE == 1) {
                *(float2*)(Cout + (size_t)gm0 * NSZ + gn) =
                    make_float2(acc[mt][nt][0], acc[mt][nt][1]);
                *(float2*)(Cout + (size_t)(gm0 + 8) * NSZ + gn) =
                    make_float2(acc[mt][nt][2], acc[mt][nt][3]);
            } else {
                const int part = gn >> 10;
                const int h = (gn & 1023) >> 6;
                const int d = gn & 63;
                float* dst = (part == 0) ? g_q : (part == 1) ? g_k : g_v;
                {
                    int b = gm0 >> 11, s = gm0 & 2047;
                    float* row = dst + ((size_t)((b * NH + h) * SQ) + s) * DK;
                    *(float2*)(row + d) = make_float2(acc[mt][nt][0], acc[mt][nt][1]);
                }
                {
                    int gm1 = gm0 + 8;
                    int b = gm1 >> 11, s = gm1 & 2047;
                    float* row = dst + ((size_t)((b * NH + h) * SQ) + s) * DK;
                    *(float2*)(row + d) = make_float2(acc[mt][nt][2], acc[mt][nt][3]);
                }
            }
        }
    }
}

// ---------------------------------------------------------------------------
// Flash-style attention with TF32 tensor cores.
// CTA = (b, h, 64-query block); K-tiles of 64; 256 threads = 8 warps (4x2).
// Warp tile for S and O: 16 rows x 32 cols.
// SMEM pitches chosen for conflict-free mma fragment loads.
// ---------------------------------------------------------------------------
#define QPITCH 68   // Qs/Ss: (4r + c) pattern -> conflict-free
#define KPITCH 68   // Ks[key][d]: B-frag (4*key + d) -> conflict-free
#define VPITCH 72   // Vs[key][d]: B-frag (8*key + d) -> conflict-free

__global__ __launch_bounds__(256)
void attn_tc(const float* __restrict__ mask) {
    extern __shared__ float sm[];
    float* Qs = sm;                       // 64*68 = 4352
    float* Ks = Qs + 64 * QPITCH;         // 4352
    float* Vs = Ks + 64 * KPITCH;         // 64*72 = 4608
    float* Ss = Vs + 64 * VPITCH;         // 4352
    float* rowm = Ss + 64 * QPITCH;       // 64
    float* rowl = rowm + 64;
    float* rowa = rowl + 64;

    const int q0 = blockIdx.x * 64;
    const int h  = blockIdx.y;
    const int b  = blockIdx.z;
    const int tid = threadIdx.x;
    const int warp = tid >> 5, lane = tid & 31;
    const int wy = warp >> 1, wx = warp & 1;     // rows wy*16, cols wx*32
    const int lr = lane >> 2, lc = lane & 3;

    const float* Qg = g_q + ((size_t)(b * NH + h) * SQ + q0) * DK;
    const float* Kg = g_k + (size_t)(b * NH + h) * SQ * DK;
    const float* Vg = g_v + (size_t)(b * NH + h) * SQ * DK;
    const float* Mg = mask + (size_t)b * SQ * SQ;
    const float* Bg = g_bias + h * NREL;

    // Load Q tile (tf32-rounded), layout [q][d]
#pragma unroll
    for (int t = 0; t < 4; t++) {
        int idx = tid + t * 256;
        int r = idx >> 4, c4 = (idx & 15) * 4;
        float4 v = *(const float4*)(Qg + r * DK + c4);
        Qs[r * QPITCH + c4 + 0] = f2tf32(v.x);
        Qs[r * QPITCH + c4 + 1] = f2tf32(v.y);
        Qs[r * QPITCH + c4 + 2] = f2tf32(v.z);
        Qs[r * QPITCH + c4 + 3] = f2tf32(v.w);
    }
    if (tid < 64) { rowm[tid] = -3.0e38f; rowl[tid] = 0.f; }

    float o[4][4];   // O warp tile: rows wy*16, cols (d) wx*32 + nt*8
#pragma unroll
    for (int nt = 0; nt < 4; nt++)
#pragma unroll
        for (int r = 0; r < 4; r++) o[nt][r] = 0.f;

    for (int k0 = 0; k0 < SQ; k0 += 64) {
        // Load K, V tiles [key][d] (tf32-rounded)
#pragma unroll
        for (int t = 0; t < 4; t++) {
            int idx = tid + t * 256;
            int r = idx >> 4, c4 = (idx & 15) * 4;
            float4 kv = *(const float4*)(Kg + (size_t)(k0 + r) * DK + c4);
            Ks[r * KPITCH + c4 + 0] = f2tf32(kv.x);
            Ks[r * KPITCH + c4 + 1] = f2tf32(kv.y);
            Ks[r * KPITCH + c4 + 2] = f2tf32(kv.z);
            Ks[r * KPITCH + c4 + 3] = f2tf32(kv.w);
            float4 vv = *(const float4*)(Vg + (size_t)(k0 + r) * DK + c4);
            Vs[r * VPITCH + c4 + 0] = f2tf32(vv.x);
            Vs[r * VPITCH + c4 + 1] = f2tf32(vv.y);
            Vs[r * VPITCH + c4 + 2] = f2tf32(vv.z);
            Vs[r * VPITCH + c4 + 3] = f2tf32(vv.w);
        }
        __syncthreads();

        // S = Q K^T : warp computes 16x32, 4 n-tiles, d-loop 8 k-steps
        float sc[4][4];
#pragma unroll
        for (int nt = 0; nt < 4; nt++)
#pragma unroll
            for (int r = 0; r < 4; r++) sc[nt][r] = 0.f;

#pragma unroll
        for (int ks = 0; ks < 8; ks++) {
            unsigned af[4], bf[4][2];
            int r0 = wy * 16 + lr;
            af[0] = __float_as_uint(Qs[r0 * QPITCH + ks * 8 + lc]);
            af[1] = __float_as_uint(Qs[(r0 + 8) * QPITCH + ks * 8 + lc]);
            af[2] = __float_as_uint(Qs[r0 * QPITCH + ks * 8 + lc + 4]);
            af[3] = __float_as_uint(Qs[(r0 + 8) * QPITCH + ks * 8 + lc + 4]);
#pragma unroll
            for (int nt = 0; nt < 4; nt++) {
                int key = wx * 32 + nt * 8 + lr;
                bf[nt][0] = __float_as_uint(Ks[key * KPITCH + ks * 8 + lc]);
                bf[nt][1] = __float_as_uint(Ks[key * KPITCH + ks * 8 + lc + 4]);
            }
#pragma unroll
            for (int nt = 0; nt < 4; nt++)
                mma_tf32(sc[nt], af, bf[nt]);
        }

        // scale + mask + bias -> Ss
        {
            int r0 = wy * 16 + lr;
            int q_0 = q0 + r0, q_1 = q_0 + 8;
#pragma unroll
            for (int nt = 0; nt < 4; nt++) {
                int col = wx * 32 + nt * 8 + 2 * lc;
                int kg = k0 + col;
                float2 m0v = *(const float2*)(Mg + (size_t)q_0 * SQ + kg);
                float2 m1v = *(const float2*)(Mg + (size_t)q_1 * SQ + kg);
                float b00 = Bg[kg - q_0 + (SQ - 1)];
                float b01 = Bg[kg + 1 - q_0 + (SQ - 1)];
                float b10 = Bg[kg - q_1 + (SQ - 1)];
                float b11 = Bg[kg + 1 - q_1 + (SQ - 1)];
                float2 w0, w1;
                w0.x = sc[nt][0] * 0.125f * m0v.x + (b00 - 10000.f * (1.f - m0v.x));
                w0.y = sc[nt][1] * 0.125f * m0v.y + (b01 - 10000.f * (1.f - m0v.y));
                w1.x = sc[nt][2] * 0.125f * m1v.x + (b10 - 10000.f * (1.f - m1v.x));
                w1.y = sc[nt][3] * 0.125f * m1v.y + (b11 - 10000.f * (1.f - m1v.y));
                *(float2*)(Ss + r0 * QPITCH + col) = w0;
                *(float2*)(Ss + (r0 + 8) * QPITCH + col) = w1;
            }
        }
        __syncthreads();

        // Online softmax: 4 lanes per row, 64 cols; writeback tf32-rounded P
        {
            int row = tid >> 2, c4 = tid & 3;
            float* srow = Ss + row * QPITCH + c4 * 16;
            float4 v0 = *(float4*)(srow);
            float4 v1 = *(float4*)(srow + 4);
            float4 v2 = *(float4*)(srow + 8);
            float4 v3 = *(float4*)(srow + 12);
            float tmax = fmaxf(fmaxf(fmaxf(v0.x, v0.y), fmaxf(v0.z, v0.w)),
                        fmaxf(fmaxf(fmaxf(v1.x, v1.y), fmaxf(v1.z, v1.w)),
                        fmaxf(fmaxf(fmaxf(v2.x, v2.y), fmaxf(v2.z, v2.w)),
                              fmaxf(fmaxf(v3.x, v3.y), fmaxf(v3.z, v3.w)))));
            tmax = fmaxf(tmax, __shfl_xor_sync(0xffffffffu, tmax, 1));
            tmax = fmaxf(tmax, __shfl_xor_sync(0xffffffffu, tmax, 2));
            float mold = rowm[row];
            float mnew = fmaxf(mold, tmax);
            float alpha = __expf(mold - mnew);
            v0.x = __expf(v0.x - mnew); v0.y = __expf(v0.y - mnew);
            v0.z = __expf(v0.z - mnew); v0.w = __expf(v0.w - mnew);
            v1.x = __expf(v1.x - mnew); v1.y = __expf(v1.y - mnew);
            v1.z = __expf(v1.z - mnew); v1.w = __expf(v1.w - mnew);
            v2.x = __expf(v2.x - mnew); v2.y = __expf(v2.y - mnew);
            v2.z = __expf(v2.z - mnew); v2.w = __expf(v2.w - mnew);
            v3.x = __expf(v3.x - mnew); v3.y = __expf(v3.y - mnew);
            v3.z = __expf(v3.z - mnew); v3.w = __expf(v3.w - mnew);
            float psum = (v0.x + v0.y + v0.z + v0.w) + (v1.x + v1.y + v1.z + v1.w)
                       + (v2.x + v2.y + v2.z + v2.w) + (v3.x + v3.y + v3.z + v3.w);
            psum += __shfl_xor_sync(0xffffffffu, psum, 1);
            psum += __shfl_xor_sync(0xffffffffu, psum, 2);
            v0.x = f2tf32(v0.x); v0.y = f2tf32(v0.y); v0.z = f2tf32(v0.z); v0.w = f2tf32(v0.w);
            v1.x = f2tf32(v1.x); v1.y = f2tf32(v1.y); v1.z = f2tf32(v1.z); v1.w = f2tf32(v1.w);
            v2.x = f2tf32(v2.x); v2.y = f2tf32(v2.y); v2.z = f2tf32(v2.z); v2.w = f2tf32(v2.w);
            v3.x = f2tf32(v3.x); v3.y = f2tf32(v3.y); v3.z = f2tf32(v3.z); v3.w = f2tf32(v3.w);
            *(float4*)(srow)      = v0;
            *(float4*)(srow + 4)  = v1;
            *(float4*)(srow + 8)  = v2;
            *(float4*)(srow + 12) = v3;
            if (c4 == 0) {
                rowl[row] = rowl[row] * alpha + psum;
                rowm[row] = mnew;
                rowa[row] = alpha;
            }
        }
        __syncthreads();

        // Rescale O, then O += P V
        {
            int r0 = wy * 16 + lr;
            float a0 = rowa[r0], a1 = rowa[r0 + 8];
#pragma unroll
            for (int nt = 0; nt < 4; nt++) {
                o[nt][0] *= a0; o[nt][1] *= a0;
                o[nt][2] *= a1; o[nt][3] *= a1;
            }
#pragma unroll
            for (int ks = 0; ks < 8; ks++) {
                unsigned af[4], bf[4][2];
                af[0] = __float_as_uint(Ss[r0 * QPITCH + ks * 8 + lc]);
                af[1] = __float_as_uint(Ss[(r0 + 8) * QPITCH + ks * 8 + lc]);
                af[2] = __float_as_uint(Ss[r0 * QPITCH + ks * 8 + lc + 4]);
                af[3] = __float_as_uint(Ss[(r0 + 8) * QPITCH + ks * 8 + lc + 4]);
#pragma unroll
                for (int nt = 0; nt < 4; nt++) {
                    int d = wx * 32 + nt * 8 + lr;
                    bf[nt][0] = __float_as_uint(Vs[(ks * 8 + lc) * VPITCH + d]);
                    bf[nt][1] = __float_as_uint(Vs[(ks * 8 + lc + 4) * VPITCH + d]);
                }
#pragma unroll
                for (int nt = 0; nt < 4; nt++)
                    mma_tf32(o[nt], af, bf[nt]);
            }
        }
        __syncthreads();
    }

    // Finalize: O / l -> g_ctx [b*S+q][h*64+d]
    {
        int r0 = wy * 16 + lr;
        float li0 = 1.0f / rowl[r0];
        float li1 = 1.0f / rowl[r0 + 8];
        int q_0 = q0 + r0, q_1 = q_0 + 8;
#pragma unroll
        for (int nt = 0; nt < 4; nt++) {
            int d = h * DK + wx * 32 + nt * 8 + 2 * lc;
            *(float2*)(g_ctx + (size_t)(b * SQ + q_0) * DMODEL + d) =
                make_float2(o[nt][0] * li0, o[nt][1] * li0);
            *(float2*)(g_ctx + (size_t)(b * SQ + q_1) * DMODEL + d) =
                make_float2(o[nt][2] * li1, o[nt][3] * li1);
        }
    }
}

// ---------------------------------------------------------------------------
extern "C" void kernel_launch(void* const* d_in, const int* in_sizes, int n_in,
                              void* d_out, int out_size) {
    (void)in_sizes; (void)n_in; (void)out_size;
    const float* hidden = (const float*)d_in[0];
    const float* mask   = (const float*)d_in[1];
    const float* Wqkv   = (const float*)d_in[2];
    const float* Wo     = (const float*)d_in[3];
    const float* emb    = (const float*)d_in[4];
    float* out = (float*)d_out;

    // 1) Bias table
    bias_kernel<<<16, 256>>>(emb);

    // 2) QKV projection (tensor cores) + head-major scatter
    gemm_tc<3072, 0><<<dim3(24, 32), 256>>>(hidden, Wqkv, nullptr);

    // 3) Attention (flash-style, tf32 mma)
    const int smem_bytes = (64 * QPITCH * 2 + 64 * KPITCH + 64 * VPITCH + 192) * 4;
    cudaFuncSetAttribute(attn_tc, cudaFuncAttributeMaxDynamicSharedMemorySize,
                         smem_bytes);
    attn_tc<<<dim3(SQ / 64, NH, BATCH), 256, smem_bytes>>>(mask);

    // 4) Output projection
    gemm_tc<1024, 1><<<dim3(8, 32), 256>>>(nullptr, Wo, out);
}

// round 3
// speedup vs baseline: 2.8256x; 1.2130x over previous
#include <cuda_runtime.h>
#include <math.h>

#define BATCH 2
#define SQ 2048
#define NH 16
#define DK 64
#define DMODEL 1024
#define NREL 4095   // relative positions -2047..2047

__device__ float g_q[BATCH*NH*SQ*DK];
__device__ float g_k[BATCH*NH*SQ*DK];
__device__ float g_v[BATCH*NH*SQ*DK];
__device__ float g_ctx[(size_t)BATCH*SQ*DMODEL];
__device__ float g_bias[NH*NREL];

// ---------------------------------------------------------------------------
__device__ __forceinline__ float f2tf32(float x) {
    unsigned r;
    asm("cvt.rna.tf32.f32 %0, %1;" : "=r"(r) : "f"(x));
    return __uint_as_float(r);
}

__device__ __forceinline__ void mma_tf32(float c[4], const unsigned a[4],
                                         const unsigned b[2]) {
    asm volatile(
        "mma.sync.aligned.m16n8k8.row.col.f32.tf32.tf32.f32 "
        "{%0,%1,%2,%3}, {%4,%5,%6,%7}, {%8,%9}, {%0,%1,%2,%3};\n"
        : "+f"(c[0]), "+f"(c[1]), "+f"(c[2]), "+f"(c[3])
        : "r"(a[0]), "r"(a[1]), "r"(a[2]), "r"(a[3]), "r"(b[0]), "r"(b[1]));
}

// ---------------------------------------------------------------------------
__global__ void bias_kernel(const float* __restrict__ emb) {
    int idx = blockIdx.x * blockDim.x + threadIdx.x;
    if (idx >= NREL) return;
    int rel = idx - (SQ - 1);
    int bucket = (rel > 0) ? 16 : 0;
    int rp = rel < 0 ? -rel : rel;
    int add;
    if (rp < 8) {
        add = rp;
    } else {
        float t = logf((float)rp * 0.125f);
        float u = t / 2.772588722239781f;
        float v = u * 8.0f;
        int w = 8 + (int)v;
        add = w < 15 ? w : 15;
    }
    bucket += add;
#pragma unroll
    for (int h = 0; h < NH; h++)
        g_bias[h * NREL + idx] = emb[bucket * NH + h];
}

// ---------------------------------------------------------------------------
// TF32 GEMM, double-buffered SMEM, 1 sync per BK=16 iter.
// CTA tile 128x128, 256 threads = 8 warps (2x4), warp tile 64x32.
// ---------------------------------------------------------------------------
#define AP 20
#define BP 136

template <int NSZ, int MODE>
__global__ __launch_bounds__(256)
void gemm_tc(const float* __restrict__ A, const float* __restrict__ B,
             float* __restrict__ Cout) {
    __shared__ float As[2][128 * AP];
    __shared__ float Bs[2][16 * BP];

    const int n0 = blockIdx.x * 128;
    const int m0 = blockIdx.y * 128;
    const int tid = threadIdx.x;
    const int warp = tid >> 5, lane = tid & 31;
    const int wy = warp >> 2, wx = warp & 3;
    const int lr = lane >> 2, lc = lane & 3;

    const float* Abase = (MODE == 0) ? A : (const float*)g_ctx;
    const float* Ap = Abase + (size_t)m0 * 1024;
    const float* Bp = B + n0;

    const int fa = 2 * tid;
    const int a_row0 = fa >> 2,       a_c0 = (fa & 3) * 4;
    const int a_row1 = (fa + 1) >> 2, a_c1 = ((fa + 1) & 3) * 4;
    const int b_row0 = fa >> 5,       b_c0 = (fa & 31) * 4;
    const int b_row1 = (fa + 1) >> 5, b_c1 = ((fa + 1) & 31) * 4;

    float acc[4][4][4];
#pragma unroll
    for (int i = 0; i < 4; i++)
#pragma unroll
        for (int j = 0; j < 4; j++)
#pragma unroll
            for (int r = 0; r < 4; r++) acc[i][j][r] = 0.f;

    float4 pa0, pa1, pb0, pb1;
    pa0 = *(const float4*)(Ap + (size_t)a_row0 * 1024 + a_c0);
    pa1 = *(const float4*)(Ap + (size_t)a_row1 * 1024 + a_c1);
    pb0 = *(const float4*)(Bp + (size_t)b_row0 * NSZ + b_c0);
    pb1 = *(const float4*)(Bp + (size_t)b_row1 * NSZ + b_c1);

#define STORE_STAGE(st)                                   \
    do {                                                  \
        float* as = As[st]; float* bs = Bs[st];           \
        as[a_row0 * AP + a_c0 + 0] = f2tf32(pa0.x);       \
        as[a_row0 * AP + a_c0 + 1] = f2tf32(pa0.y);       \
        as[a_row0 * AP + a_c0 + 2] = f2tf32(pa0.z);       \
        as[a_row0 * AP + a_c0 + 3] = f2tf32(pa0.w);       \
        as[a_row1 * AP + a_c1 + 0] = f2tf32(pa1.x);       \
        as[a_row1 * AP + a_c1 + 1] = f2tf32(pa1.y);       \
        as[a_row1 * AP + a_c1 + 2] = f2tf32(pa1.z);       \
        as[a_row1 * AP + a_c1 + 3] = f2tf32(pa1.w);       \
        bs[b_row0 * BP + b_c0 + 0] = f2tf32(pb0.x);       \
        bs[b_row0 * BP + b_c0 + 1] = f2tf32(pb0.y);       \
        bs[b_row0 * BP + b_c0 + 2] = f2tf32(pb0.z);       \
        bs[b_row0 * BP + b_c0 + 3] = f2tf32(pb0.w);       \
        bs[b_row1 * BP + b_c1 + 0] = f2tf32(pb1.x);       \
        bs[b_row1 * BP + b_c1 + 1] = f2tf32(pb1.y);       \
        bs[b_row1 * BP + b_c1 + 2] = f2tf32(pb1.z);       \
        bs[b_row1 * BP + b_c1 + 3] = f2tf32(pb1.w);       \
    } while (0)

    STORE_STAGE(0);
    int s = 0;

    for (int k0 = 0; k0 < 1024; k0 += 16) {
        __syncthreads();
        const bool more = (k0 + 16 < 1024);
        if (more) {
            pa0 = *(const float4*)(Ap + (size_t)a_row0 * 1024 + k0 + 16 + a_c0);
            pa1 = *(const float4*)(Ap + (size_t)a_row1 * 1024 + k0 + 16 + a_c1);
            pb0 = *(const float4*)(Bp + (size_t)(k0 + 16 + b_row0) * NSZ + b_c0);
            pb1 = *(const float4*)(Bp + (size_t)(k0 + 16 + b_row1) * NSZ + b_c1);
        }
        const float* as = As[s];
        const float* bs = Bs[s];
#pragma unroll
        for (int ks = 0; ks < 2; ks++) {
            unsigned af[4][4], bf[4][2];
#pragma unroll
            for (int mt = 0; mt < 4; mt++) {
                int r0 = wy * 64 + mt * 16 + lr;
                af[mt][0] = __float_as_uint(as[r0 * AP + ks * 8 + lc]);
                af[mt][1] = __float_as_uint(as[(r0 + 8) * AP + ks * 8 + lc]);
                af[mt][2] = __float_as_uint(as[r0 * AP + ks * 8 + lc + 4]);
                af[mt][3] = __float_as_uint(as[(r0 + 8) * AP + ks * 8 + lc + 4]);
            }
#pragma unroll
            for (int nt = 0; nt < 4; nt++) {
                int n = wx * 32 + nt * 8 + lr;
                bf[nt][0] = __float_as_uint(bs[(ks * 8 + lc) * BP + n]);
                bf[nt][1] = __float_as_uint(bs[(ks * 8 + lc + 4) * BP + n]);
            }
#pragma unroll
            for (int mt = 0; mt < 4; mt++)
#pragma unroll
                for (int nt = 0; nt < 4; nt++)
                    mma_tf32(acc[mt][nt], af[mt], bf[nt]);
        }
        if (more) STORE_STAGE(s ^ 1);
        s ^= 1;
    }
#undef STORE_STAGE

#pragma unroll
    for (int mt = 0; mt < 4; mt++) {
        int gm0 = m0 + wy * 64 + mt * 16 + lr;
#pragma unroll
        for (int nt = 0; nt < 4; nt++) {
            int gn = n0 + wx * 32 + nt * 8 + 2 * lc;
            if (MODE == 1) {
                *(float2*)(Cout + (size_t)gm0 * NSZ + gn) =
                    make_float2(acc[mt][nt][0], acc[mt][nt][1]);
                *(float2*)(Cout + (size_t)(gm0 + 8) * NSZ + gn) =
                    make_float2(acc[mt][nt][2], acc[mt][nt][3]);
            } else {
                const int part = gn >> 10;
                const int h = (gn & 1023) >> 6;
                const int d = gn & 63;
                float* dst = (part == 0) ? g_q : (part == 1) ? g_k : g_v;
                {
                    int b = gm0 >> 11, sq = gm0 & 2047;
                    float* row = dst + ((size_t)((b * NH + h) * SQ) + sq) * DK;
                    *(float2*)(row + d) = make_float2(acc[mt][nt][0], acc[mt][nt][1]);
                }
                {
                    int gm1 = gm0 + 8;
                    int b = gm1 >> 11, sq = gm1 & 2047;
                    float* row = dst + ((size_t)((b * NH + h) * SQ) + sq) * DK;
                    *(float2*)(row + d) = make_float2(acc[mt][nt][2], acc[mt][nt][3]);
                }
            }
        }
    }
}

// ---------------------------------------------------------------------------
// Flash attention, BQ=128, BKV=64. 8 warps; warp owns 16 q-rows x all 64 keys.
// Softmax entirely in registers (rows live within one warp's 4-lane groups).
// P -> A-fragment conversion via warp shuffles.
// ---------------------------------------------------------------------------
#define BQ 128
#define BKV 64
#define QP 68
#define KP 68
#define VP 72

__global__ __launch_bounds__(256)
void attn_tc(const float* __restrict__ mask) {
    extern __shared__ float sm[];
    float* Qs  = sm;                 // 128*68
    float* Ks  = Qs + BQ * QP;       // 64*68
    float* Vs  = Ks + BKV * KP;      // 64*72
    float* Bsm = Vs + BKV * VP;      // 192

    const int q0 = blockIdx.x * BQ;
    const int h  = blockIdx.y;
    const int b  = blockIdx.z;
    const int tid = threadIdx.x;
    const int warp = tid >> 5, lane = tid & 31;
    const int lr = lane >> 2, lc = lane & 3;
    const int r0 = warp * 16 + lr;       // q-rows (tile-local)
    const int r1 = r0 + 8;

    const float* Qg = g_q + ((size_t)(b * NH + h) * SQ + q0) * DK;
    const float* Kg = g_k + (size_t)(b * NH + h) * SQ * DK;
    const float* Vg = g_v + (size_t)(b * NH + h) * SQ * DK;
    const float* Mg = mask + (size_t)b * SQ * SQ;
    const float* Bg = g_bias + h * NREL;

    // Load Q tile (tf32) [q][d]
#pragma unroll
    for (int t = 0; t < 8; t++) {
        int f = tid + t * 256;
        int r = f >> 4, c4 = (f & 15) * 4;
        float4 v = *(const float4*)(Qg + r * DK + c4);
        Qs[r * QP + c4 + 0] = f2tf32(v.x);
        Qs[r * QP + c4 + 1] = f2tf32(v.y);
        Qs[r * QP + c4 + 2] = f2tf32(v.z);
        Qs[r * QP + c4 + 3] = f2tf32(v.w);
    }

    float m0 = -3.0e38f, m1 = -3.0e38f, l0 = 0.f, l1 = 0.f;
    float o[8][4];
#pragma unroll
    for (int nt = 0; nt < 8; nt++)
#pragma unroll
        for (int r = 0; r < 4; r++) o[nt][r] = 0.f;

    const unsigned FULL = 0xffffffffu;
    const int src0 = (lane & 28) | (lc >> 1);
    const int src1 = src0 + 2;
    const bool odd = (lc & 1) != 0;

    for (int k0 = 0; k0 < SQ; k0 += BKV) {
        __syncthreads();
        // Load K/V tiles (tf32) [key][d] + bias window
#pragma unroll
        for (int t = 0; t < 4; t++) {
            int f = tid + t * 256;
            int r = f >> 4, c4 = (f & 15) * 4;
            float4 kv = *(const float4*)(Kg + (size_t)(k0 + r) * DK + c4);
            Ks[r * KP + c4 + 0] = f2tf32(kv.x);
            Ks[r * KP + c4 + 1] = f2tf32(kv.y);
            Ks[r * KP + c4 + 2] = f2tf32(kv.z);
            Ks[r * KP + c4 + 3] = f2tf32(kv.w);
            float4 vv = *(const float4*)(Vg + (size_t)(k0 + r) * DK + c4);
            Vs[r * VP + c4 + 0] = f2tf32(vv.x);
            Vs[r * VP + c4 + 1] = f2tf32(vv.y);
            Vs[r * VP + c4 + 2] = f2tf32(vv.z);
            Vs[r * VP + c4 + 3] = f2tf32(vv.w);
        }
        if (tid < 191)
            Bsm[tid] = Bg[k0 - q0 + tid - 127 + (SQ - 1)];
        __syncthreads();

        // S = Q K^T : 16x64 per warp
        float sc[8][4];
#pragma unroll
        for (int nt = 0; nt < 8; nt++)
#pragma unroll
            for (int r = 0; r < 4; r++) sc[nt][r] = 0.f;

#pragma unroll
        for (int ks = 0; ks < 8; ks++) {
            unsigned af[4], bf[8][2];
            af[0] = __float_as_uint(Qs[r0 * QP + ks * 8 + lc]);
            af[1] = __float_as_uint(Qs[r1 * QP + ks * 8 + lc]);
            af[2] = __float_as_uint(Qs[r0 * QP + ks * 8 + lc + 4]);
            af[3] = __float_as_uint(Qs[r1 * QP + ks * 8 + lc + 4]);
#pragma unroll
            for (int nt = 0; nt < 8; nt++) {
                int key = nt * 8 + lr;
                bf[nt][0] = __float_as_uint(Ks[key * KP + ks * 8 + lc]);
                bf[nt][1] = __float_as_uint(Ks[key * KP + ks * 8 + lc + 4]);
            }
#pragma unroll
            for (int nt = 0; nt < 8; nt++)
                mma_tf32(sc[nt], af, bf[nt]);
        }

        // scale + mask + bias (registers)
        {
            int gq0 = q0 + r0, gq1 = q0 + r1;
#pragma unroll
            for (int nt = 0; nt < 8; nt++) {
                int col = nt * 8 + 2 * lc;
                int kg = k0 + col;
                float2 mv0 = *(const float2*)(Mg + (size_t)gq0 * SQ + kg);
                float2 mv1 = *(const float2*)(Mg + (size_t)gq1 * SQ + kg);
                float b00 = Bsm[col - r0 + 127];
                float b01 = Bsm[col + 1 - r0 + 127];
                float b10 = Bsm[col - r1 + 127];
                float b11 = Bsm[col + 1 - r1 + 127];
                sc[nt][0] = sc[nt][0] * 0.125f * mv0.x + (b00 - 10000.f * (1.f - mv0.x));
                sc[nt][1] = sc[nt][1] * 0.125f * mv0.y + (b01 - 10000.f * (1.f - mv0.y));
                sc[nt][2] = sc[nt][2] * 0.125f * mv1.x + (b10 - 10000.f * (1.f - mv1.x));
                sc[nt][3] = sc[nt][3] * 0.125f * mv1.y + (b11 - 10000.f * (1.f - mv1.y));
            }
        }

        // Online softmax in registers
        float tm0 = -3.0e38f, tm1 = -3.0e38f;
#pragma unroll
        for (int nt = 0; nt < 8; nt++) {
            tm0 = fmaxf(tm0, fmaxf(sc[nt][0], sc[nt][1]));
            tm1 = fmaxf(tm1, fmaxf(sc[nt][2], sc[nt][3]));
        }
        tm0 = fmaxf(tm0, __shfl_xor_sync(FULL, tm0, 1));
        tm0 = fmaxf(tm0, __shfl_xor_sync(FULL, tm0, 2));
        tm1 = fmaxf(tm1, __shfl_xor_sync(FULL, tm1, 1));
        tm1 = fmaxf(tm1, __shfl_xor_sync(FULL, tm1, 2));
        float mn0 = fmaxf(m0, tm0), mn1 = fmaxf(m1, tm1);
        float al0 = __expf(m0 - mn0), al1 = __expf(m1 - mn1);
        m0 = mn0; m1 = mn1;
        float ps0 = 0.f, ps1 = 0.f;
#pragma unroll
        for (int nt = 0; nt < 8; nt++) {
            float e0 = __expf(sc[nt][0] - mn0);
            float e1 = __expf(sc[nt][1] - mn0);
            float e2 = __expf(sc[nt][2] - mn1);
            float e3 = __expf(sc[nt][3] - mn1);
            ps0 += e0 + e1; ps1 += e2 + e3;
            sc[nt][0] = f2tf32(e0); sc[nt][1] = f2tf32(e1);
            sc[nt][2] = f2tf32(e2); sc[nt][3] = f2tf32(e3);
        }
        ps0 += __shfl_xor_sync(FULL, ps0, 1);
        ps0 += __shfl_xor_sync(FULL, ps0, 2);
        ps1 += __shfl_xor_sync(FULL, ps1, 1);
        ps1 += __shfl_xor_sync(FULL, ps1, 2);
        l0 = l0 * al0 + ps0;
        l1 = l1 * al1 + ps1;

        // Rescale O
#pragma unroll
        for (int nt = 0; nt < 8; nt++) {
            o[nt][0] *= al0; o[nt][1] *= al0;
            o[nt][2] *= al1; o[nt][3] *= al1;
        }

        // O += P V : permute P C-frag -> A-frag via shuffles, then mma
#pragma unroll
        for (int ks = 0; ks < 8; ks++) {
            float t00 = __shfl_sync(FULL, sc[ks][0], src0);
            float t01 = __shfl_sync(FULL, sc[ks][1], src0);
            float t10 = __shfl_sync(FULL, sc[ks][2], src0);
            float t11 = __shfl_sync(FULL, sc[ks][3], src0);
            float u00 = __shfl_sync(FULL, sc[ks][0], src1);
            float u01 = __shfl_sync(FULL, sc[ks][1], src1);
            float u10 = __shfl_sync(FULL, sc[ks][2], src1);
            float u11 = __shfl_sync(FULL, sc[ks][3], src1);
            unsigned af[4];
            af[0] = __float_as_uint(odd ? t01 : t00);
            af[1] = __float_as_uint(odd ? t11 : t10);
            af[2] = __float_as_uint(odd ? u01 : u00);
            af[3] = __float_as_uint(odd ? u11 : u10);
#pragma unroll
            for (int nt = 0; nt < 8; nt++) {
                int d = nt * 8 + lr;
                unsigned bf[2];
                bf[0] = __float_as_uint(Vs[(ks * 8 + lc) * VP + d]);
                bf[1] = __float_as_uint(Vs[(ks * 8 + lc + 4) * VP + d]);
                mma_tf32(o[nt], af, bf);
            }
        }
    }

    // Finalize: O / l -> g_ctx [b*S+q][h*64+d]
    {
        float li0 = 1.0f / l0, li1 = 1.0f / l1;
        int gq0 = q0 + r0, gq1 = q0 + r1;
#pragma unroll
        for (int nt = 0; nt < 8; nt++) {
            int d = h * DK + nt * 8 + 2 * lc;
            *(float2*)(g_ctx + (size_t)(b * SQ + gq0) * DMODEL + d) =
                make_float2(o[nt][0] * li0, o[nt][1] * li0);
            *(float2*)(g_ctx + (size_t)(b * SQ + gq1) * DMODEL + d) =
                make_float2(o[nt][2] * li1, o[nt][3] * li1);
        }
    }
}

// ---------------------------------------------------------------------------
extern "C" void kernel_launch(void* const* d_in, const int* in_sizes, int n_in,
                              void* d_out, int out_size) {
    (void)in_sizes; (void)n_in; (void)out_size;
    const float* hidden = (const float*)d_in[0];
    const float* mask   = (const float*)d_in[1];
    const float* Wqkv   = (const float*)d_in[2];
    const float* Wo     = (const float*)d_in[3];
    const float* emb    = (const float*)d_in[4];
    float* out = (float*)d_out;

    bias_kernel<<<16, 256>>>(emb);

    gemm_tc<3072, 0><<<dim3(24, 32), 256>>>(hidden, Wqkv, nullptr);

    const int smem_bytes = (BQ * QP + BKV * KP + BKV * VP + 192) * 4;
    cudaFuncSetAttribute(attn_tc, cudaFuncAttributeMaxDynamicSharedMemorySize,
                         smem_bytes);
    attn_tc<<<dim3(SQ / BQ, NH, BATCH), 256, smem_bytes>>>(mask);

    gemm_tc<1024, 1><<<dim3(8, 32), 256>>>(nullptr, Wo, out);
}